// round 2
// baseline (speedup 1.0000x reference)
#include <cuda_runtime.h>
#include <cuda_bf16.h>
#include <math.h>

// ---------------- problem constants ----------------
#define NN    50000
#define EE    800000
#define EP    850000          // EE + NN self loops
#define INC   1024
#define H1    4
#define C1    64
#define HC1   256             // H1*C1
#define OC    64
#define NEG_SLOPE 0.2f

// ---------------- scratch (device globals; no allocation allowed) ----------
__device__ float    g_h1[(size_t)NN * HC1];     // layer1 projected features; reused as x2 after elu
__device__ float    g_out1[(size_t)NN * HC1];   // layer1 aggregated output
__device__ float    g_as1[NN * H1];
__device__ float    g_ad1[NN * H1];
__device__ float    g_e1[(size_t)EP * H1];      // e -> exp -> alpha (in place)
__device__ unsigned g_m1[NN * H1];
__device__ float    g_d1[NN * H1];

__device__ float    g_h2[(size_t)NN * OC];
__device__ float    g_as2[NN];
__device__ float    g_ad2[NN];
__device__ float    g_e2[EP];
__device__ unsigned g_m2[NN];
__device__ float    g_d2[NN];

// monotonic float<->uint encoding for atomicMax on floats
__device__ __forceinline__ unsigned fenc(float f) {
    unsigned u = __float_as_uint(f);
    return (u & 0x80000000u) ? ~u : (u | 0x80000000u);
}
__device__ __forceinline__ float fdec(unsigned e) {
    unsigned u = (e & 0x80000000u) ? (e ^ 0x80000000u) : ~e;
    return __uint_as_float(u);
}
#define ENC_NEG_INF 0x007FFFFFu   // fenc(-inf)

// ---------------- init ----------------
__global__ void k_init(float* dout) {
    int i = blockIdx.x * blockDim.x + threadIdx.x;
    int stride = gridDim.x * blockDim.x;
    for (int j = i; j < NN * HC1; j += stride) g_out1[j] = 0.f;
    for (int j = i; j < NN * H1;  j += stride) { g_m1[j] = ENC_NEG_INF; g_d1[j] = 0.f; }
    for (int j = i; j < NN;       j += stride) { g_m2[j] = ENC_NEG_INF; g_d2[j] = 0.f; }
    for (int j = i; j < NN * OC;  j += stride) dout[j] = 0.f;
}

// ---------------- SGEMM: C[m,n] = sum_k A[m,k] * B[n,k]  (B row-major [N,K]) --
#define BM 64
#define BN 64
#define BK 16
#define TM 4
#define TN 4
__global__ __launch_bounds__(256) void k_sgemm_nt(
    const float* __restrict__ A, const float* __restrict__ B,
    float* __restrict__ C, int M, int N, int K)
{
    __shared__ float As[BK][BM + 1];
    __shared__ float Bs[BK][BN + 1];
    int bm = blockIdx.y * BM, bn = blockIdx.x * BN;
    int tid = threadIdx.x;
    int tx = tid & 15;          // 16 cols of threads
    int ty = tid >> 4;          // 16 rows of threads
    float acc[TM][TN] = {};
    for (int k0 = 0; k0 < K; k0 += BK) {
        #pragma unroll
        for (int t = tid; t < BM * BK; t += 256) {
            int r = t >> 4, c = t & 15;
            int gm = bm + r;
            As[c][r] = (gm < M) ? A[(size_t)gm * K + k0 + c] : 0.f;
        }
        #pragma unroll
        for (int t = tid; t < BN * BK; t += 256) {
            int r = t >> 4, c = t & 15;
            int gn = bn + r;
            Bs[c][r] = (gn < N) ? B[(size_t)gn * K + k0 + c] : 0.f;
        }
        __syncthreads();
        #pragma unroll
        for (int k = 0; k < BK; k++) {
            float ra[TM], rb[TN];
            #pragma unroll
            for (int i = 0; i < TM; i++) ra[i] = As[k][ty * TM + i];
            #pragma unroll
            for (int j = 0; j < TN; j++) rb[j] = Bs[k][tx * TN + j];
            #pragma unroll
            for (int i = 0; i < TM; i++)
                #pragma unroll
                for (int j = 0; j < TN; j++) acc[i][j] += ra[i] * rb[j];
        }
        __syncthreads();
    }
    #pragma unroll
    for (int i = 0; i < TM; i++) {
        int gm = bm + ty * TM + i;
        if (gm >= M) continue;
        #pragma unroll
        for (int j = 0; j < TN; j++) {
            int gn = bn + tx * TN + j;
            if (gn < N) C[(size_t)gm * N + gn] = acc[i][j];
        }
    }
}

// ---------------- per-(node,head) attention coefficients: warp reductions ----
__global__ void k_alpha(const float* __restrict__ h,
                        const float* __restrict__ a_s, const float* __restrict__ a_d,
                        float* __restrict__ as_out, float* __restrict__ ad_out,
                        int n_nh, int Hh, int Cc)
{
    int warp = (blockIdx.x * blockDim.x + threadIdx.x) >> 5;
    int lane = threadIdx.x & 31;
    if (warp >= n_nh) return;                 // warp per (node, head)
    int hh = warp % Hh;
    const float* hp  = h + (size_t)warp * Cc; // h laid out [node, head, C] contiguous
    const float* asp = a_s + hh * Cc;
    const float* adp = a_d + hh * Cc;
    float s = 0.f, d = 0.f;
    for (int c = lane; c < Cc; c += 32) {
        float v = hp[c];
        s += v * asp[c];
        d += v * adp[c];
    }
    #pragma unroll
    for (int o = 16; o > 0; o >>= 1) {
        s += __shfl_xor_sync(0xFFFFFFFFu, s, o);
        d += __shfl_xor_sync(0xFFFFFFFFu, d, o);
    }
    if (lane == 0) { as_out[warp] = s; ad_out[warp] = d; }
}

// ---------------- edge pass 1: e = leaky_relu(as[src]+ad[dst]); segment max --
__global__ void k_edge_max(const int* __restrict__ ei,
                           const float* __restrict__ as, const float* __restrict__ ad,
                           float* __restrict__ e_out, unsigned* __restrict__ m, int Hh)
{
    int idx = blockIdx.x * blockDim.x + threadIdx.x;
    int tot = EP * Hh;
    if (idx >= tot) return;
    int e = idx / Hh, hh = idx - e * Hh;
    int s, dn;
    if (e < EE) { s = ei[e]; dn = ei[EE + e]; }
    else        { s = e - EE; dn = s; }
    float v = as[s * Hh + hh] + ad[dn * Hh + hh];
    v = (v > 0.f) ? v : NEG_SLOPE * v;
    e_out[idx] = v;
    atomicMax(&m[dn * Hh + hh], fenc(v));
}

// ---------------- edge pass 2: ex = exp(e - m[dst]); segment sum -------------
__global__ void k_edge_exp(const int* __restrict__ ei,
                           float* __restrict__ e_buf,
                           const unsigned* __restrict__ m, float* __restrict__ denom, int Hh)
{
    int idx = blockIdx.x * blockDim.x + threadIdx.x;
    int tot = EP * Hh;
    if (idx >= tot) return;
    int e = idx / Hh, hh = idx - e * Hh;
    int dn;
    if (e < EE) dn = ei[EE + e];
    else        dn = e - EE;
    float mx = fdec(m[dn * Hh + hh]);
    float ex = __expf(e_buf[idx] - mx);
    e_buf[idx] = ex;
    atomicAdd(&denom[dn * Hh + hh], ex);
}

// ---------------- edge pass 3: alpha = ex / denom[dst] (in place) ------------
__global__ void k_edge_norm(const int* __restrict__ ei,
                            float* __restrict__ e_buf,
                            const float* __restrict__ denom, int Hh)
{
    int idx = blockIdx.x * blockDim.x + threadIdx.x;
    int tot = EP * Hh;
    if (idx >= tot) return;
    int e = idx / Hh, hh = idx - e * Hh;
    int dn;
    if (e < EE) dn = ei[EE + e];
    else        dn = e - EE;
    e_buf[idx] = e_buf[idx] / denom[dn * Hh + hh];
}

// ---------------- edge pass 4: out[dst] += alpha * h[src] --------------------
__global__ void k_agg(const int* __restrict__ ei,
                      const float* __restrict__ alpha,
                      const float* __restrict__ h,
                      float* __restrict__ out, int Hh, int Cc)
{
    int hc_w = Hh * Cc;
    int idx = blockIdx.x * blockDim.x + threadIdx.x;
    int e = idx / hc_w;
    int hc = idx - e * hc_w;
    if (e >= EP) return;
    int hh = hc / Cc;
    int s, dn;
    if (e < EE) { s = ei[e]; dn = ei[EE + e]; }
    else        { s = e - EE; dn = s; }
    float a = alpha[(size_t)e * Hh + hh];
    atomicAdd(&out[(size_t)dn * hc_w + hc], a * h[(size_t)s * hc_w + hc]);
}

// ---------------- elu(out1 + b1) -> x2 (stored over g_h1) --------------------
__global__ void k_elu_bias(const float* __restrict__ in, const float* __restrict__ b,
                           float* __restrict__ out, int total, int cols)
{
    int i = blockIdx.x * blockDim.x + threadIdx.x;
    if (i >= total) return;
    float v = in[i] + b[i % cols];
    out[i] = (v > 0.f) ? v : (expm1f(v));
}

// ---------------- final bias add ---------------------------------------------
__global__ void k_bias(float* __restrict__ out, const float* __restrict__ b,
                       int total, int cols)
{
    int i = blockIdx.x * blockDim.x + threadIdx.x;
    if (i >= total) return;
    out[i] += b[i % cols];
}

// =============================================================================
extern "C" void kernel_launch(void* const* d_in, const int* in_sizes, int n_in,
                              void* d_out, int out_size)
{
    const float* x     = (const float*)d_in[0];
    const int*   ei    = (const int*)d_in[1];      // int32! (JAX x64 disabled)
    const float* W1    = (const float*)d_in[2];
    const float* a_s1  = (const float*)d_in[3];
    const float* a_d1  = (const float*)d_in[4];
    const float* b1    = (const float*)d_in[5];
    const float* W2    = (const float*)d_in[6];
    const float* a_s2  = (const float*)d_in[7];
    const float* a_d2  = (const float*)d_in[8];
    const float* b2    = (const float*)d_in[9];
    float*       out   = (float*)d_out;

    // device addresses of scratch globals
    float *h1, *out1, *as1, *ad1, *e1, *d1, *h2, *as2, *ad2, *e2, *d2;
    unsigned *m1, *m2;
    cudaGetSymbolAddress((void**)&h1,   g_h1);
    cudaGetSymbolAddress((void**)&out1, g_out1);
    cudaGetSymbolAddress((void**)&as1,  g_as1);
    cudaGetSymbolAddress((void**)&ad1,  g_ad1);
    cudaGetSymbolAddress((void**)&e1,   g_e1);
    cudaGetSymbolAddress((void**)&m1,   g_m1);
    cudaGetSymbolAddress((void**)&d1,   g_d1);
    cudaGetSymbolAddress((void**)&h2,   g_h2);
    cudaGetSymbolAddress((void**)&as2,  g_as2);
    cudaGetSymbolAddress((void**)&ad2,  g_ad2);
    cudaGetSymbolAddress((void**)&e2,   g_e2);
    cudaGetSymbolAddress((void**)&m2,   g_m2);
    cudaGetSymbolAddress((void**)&d2,   g_d2);

    // init accumulators / output
    k_init<<<2048, 256>>>(out);

    // ---- layer 1 ----
    {
        dim3 grid(HC1 / BN, (NN + BM - 1) / BM);
        k_sgemm_nt<<<grid, 256>>>(x, W1, h1, NN, HC1, INC);
    }
    {
        int warps = NN * H1;
        k_alpha<<<(warps * 32 + 255) / 256, 256>>>(h1, a_s1, a_d1, as1, ad1, warps, H1, C1);
    }
    {
        int tot = EP * H1;
        int blk = (tot + 255) / 256;
        k_edge_max <<<blk, 256>>>(ei, as1, ad1, e1, m1, H1);
        k_edge_exp <<<blk, 256>>>(ei, e1, m1, d1, H1);
        k_edge_norm<<<blk, 256>>>(ei, e1, d1, H1);
    }
    {
        long long tot = (long long)EP * HC1;
        int blk = (int)((tot + 255) / 256);
        k_agg<<<blk, 256>>>(ei, e1, h1, out1, H1, C1);
    }
    // elu(out1 + b1) -> x2 (stored in g_h1; h1 contents no longer needed)
    {
        int tot = NN * HC1;
        k_elu_bias<<<(tot + 255) / 256, 256>>>(out1, b1, h1, tot, HC1);
    }

    // ---- layer 2 ----
    {
        dim3 grid(OC / BN, (NN + BM - 1) / BM);
        k_sgemm_nt<<<grid, 256>>>(h1, W2, h2, NN, OC, HC1);
    }
    {
        int warps = NN;  // H=1
        k_alpha<<<(warps * 32 + 255) / 256, 256>>>(h2, a_s2, a_d2, as2, ad2, warps, 1, OC);
    }
    {
        int tot = EP;
        int blk = (tot + 255) / 256;
        k_edge_max <<<blk, 256>>>(ei, as2, ad2, e2, m2, 1);
        k_edge_exp <<<blk, 256>>>(ei, e2, m2, d2, 1);
        k_edge_norm<<<blk, 256>>>(ei, e2, d2, 1);
    }
    {
        long long tot = (long long)EP * OC;
        int blk = (int)((tot + 255) / 256);
        k_agg<<<blk, 256>>>(ei, e2, h2, out, 1, OC);
    }
    {
        int tot = NN * OC;
        k_bias<<<(tot + 255) / 256, 256>>>(out, b2, tot, OC);
    }
}

// round 3
// speedup vs baseline: 1.9158x; 1.9158x over previous
#include <cuda_runtime.h>
#include <cuda_bf16.h>
#include <math.h>

// ---------------- problem constants ----------------
#define NN    50000
#define EE    800000
#define EP    850000          // EE + NN self loops
#define INC   1024
#define H1    4
#define C1    64
#define HC1   256             // H1*C1
#define OC    64
#define NEG_SLOPE 0.2f

// ---------------- scratch (device globals) ----------------
__device__ float    g_h1[(size_t)NN * HC1];
__device__ float    g_out1[(size_t)NN * HC1];
__device__ float    g_as1[NN * H1];
__device__ float    g_ad1[NN * H1];
__device__ float    g_e1[(size_t)EP * H1];
__device__ unsigned g_m1[NN * H1];
__device__ float    g_d1[NN * H1];

__device__ float    g_h2[(size_t)NN * OC];
__device__ float    g_as2[NN];
__device__ float    g_ad2[NN];
__device__ float    g_e2[EP];
__device__ unsigned g_m2[NN];
__device__ float    g_d2[NN];

// monotonic float<->uint encoding for atomicMax on floats
__device__ __forceinline__ unsigned fenc(float f) {
    unsigned u = __float_as_uint(f);
    return (u & 0x80000000u) ? ~u : (u | 0x80000000u);
}
__device__ __forceinline__ float fdec(unsigned e) {
    unsigned u = (e & 0x80000000u) ? (e ^ 0x80000000u) : ~e;
    return __uint_as_float(u);
}
#define ENC_NEG_INF 0x007FFFFFu   // fenc(-inf)

// vectorized fire-and-forget global reduction
__device__ __forceinline__ void red_add_v4(float* p, float4 v) {
    asm volatile("red.global.add.v4.f32 [%0], {%1,%2,%3,%4};"
                 :: "l"(p), "f"(v.x), "f"(v.y), "f"(v.z), "f"(v.w) : "memory");
}

// ---------------- init ----------------
__global__ void k_init(float* dout) {
    int i = blockIdx.x * blockDim.x + threadIdx.x;
    int stride = gridDim.x * blockDim.x;
    float4 z = make_float4(0.f, 0.f, 0.f, 0.f);
    for (int j = i; j < NN * HC1 / 4; j += stride) ((float4*)g_out1)[j] = z;
    for (int j = i; j < NN * H1;  j += stride) { g_m1[j] = ENC_NEG_INF; g_d1[j] = 0.f; }
    for (int j = i; j < NN;       j += stride) { g_m2[j] = ENC_NEG_INF; g_d2[j] = 0.f; }
    for (int j = i; j < NN * OC / 4; j += stride) ((float4*)dout)[j] = z;
}

// ---------------- SGEMM 128x128x8: C[m,n] = sum_k A[m,k]*B[n,k] --------------
#define GBM 128
#define GBN 128
#define GBK 8
#define SAS 132     // padded row stride (floats)

__global__ __launch_bounds__(256) void k_sgemm128(
    const float* __restrict__ A, const float* __restrict__ B,
    float* __restrict__ C, int M, int N, int K)
{
    __shared__ float As[2][GBK][SAS];
    __shared__ float Bs[2][GBK][SAS];
    int tid = threadIdx.x;
    int bm = blockIdx.y * GBM, bn = blockIdx.x * GBN;
    int lr = tid >> 1;            // load row 0..127
    int lk = (tid & 1) * 4;       // k sub-offset 0 or 4
    int tx = tid & 15, ty = tid >> 4;
    int tx4 = tx * 4, ty4 = ty * 4;
    float c[8][8] = {};
    int nt = K / GBK;
    float4 ra, rb;
    const float4 zero4 = make_float4(0.f, 0.f, 0.f, 0.f);

    // prologue: tile 0
    {
        int gm = bm + lr;
        ra = (gm < M) ? *(const float4*)(A + (size_t)gm * K + lk) : zero4;
        int gn = bn + lr;
        rb = (gn < N) ? *(const float4*)(B + (size_t)gn * K + lk) : zero4;
        As[0][lk + 0][lr] = ra.x; As[0][lk + 1][lr] = ra.y;
        As[0][lk + 2][lr] = ra.z; As[0][lk + 3][lr] = ra.w;
        Bs[0][lk + 0][lr] = rb.x; Bs[0][lk + 1][lr] = rb.y;
        Bs[0][lk + 2][lr] = rb.z; Bs[0][lk + 3][lr] = rb.w;
    }
    __syncthreads();

    int cur = 0;
    for (int t = 0; t < nt; t++) {
        bool more = (t + 1 < nt);
        if (more) {
            int k0n = (t + 1) * GBK;
            int gm = bm + lr;
            ra = (gm < M) ? *(const float4*)(A + (size_t)gm * K + k0n + lk) : zero4;
            int gn = bn + lr;
            rb = (gn < N) ? *(const float4*)(B + (size_t)gn * K + k0n + lk) : zero4;
        }
        #pragma unroll
        for (int k = 0; k < GBK; k++) {
            float4 a0 = *(const float4*)&As[cur][k][ty4];
            float4 a1 = *(const float4*)&As[cur][k][ty4 + 64];
            float4 b0 = *(const float4*)&Bs[cur][k][tx4];
            float4 b1 = *(const float4*)&Bs[cur][k][tx4 + 64];
            float av[8] = {a0.x, a0.y, a0.z, a0.w, a1.x, a1.y, a1.z, a1.w};
            float bv[8] = {b0.x, b0.y, b0.z, b0.w, b1.x, b1.y, b1.z, b1.w};
            #pragma unroll
            for (int i = 0; i < 8; i++)
                #pragma unroll
                for (int j = 0; j < 8; j++) c[i][j] += av[i] * bv[j];
        }
        if (more) {
            int nx = cur ^ 1;
            As[nx][lk + 0][lr] = ra.x; As[nx][lk + 1][lr] = ra.y;
            As[nx][lk + 2][lr] = ra.z; As[nx][lk + 3][lr] = ra.w;
            Bs[nx][lk + 0][lr] = rb.x; Bs[nx][lk + 1][lr] = rb.y;
            Bs[nx][lk + 2][lr] = rb.z; Bs[nx][lk + 3][lr] = rb.w;
            __syncthreads();
            cur = nx;
        }
    }

    // store (quadrant layout)
    #pragma unroll
    for (int i = 0; i < 8; i++) {
        int gm = bm + ((i < 4) ? (ty4 + i) : (60 + ty4 + i));
        if (gm >= M) continue;
        int gn0 = bn + tx4;
        if (gn0 + 3 < N)
            *(float4*)&C[(size_t)gm * N + gn0] =
                make_float4(c[i][0], c[i][1], c[i][2], c[i][3]);
        int gn1 = bn + 64 + tx4;
        if (gn1 + 3 < N)
            *(float4*)&C[(size_t)gm * N + gn1] =
                make_float4(c[i][4], c[i][5], c[i][6], c[i][7]);
    }
}

// ---------------- per-(node,head) attention coefficients ---------------------
__global__ void k_alpha(const float* __restrict__ h,
                        const float* __restrict__ a_s, const float* __restrict__ a_d,
                        float* __restrict__ as_out, float* __restrict__ ad_out,
                        int n_nh, int Hh, int Cc)
{
    int warp = (blockIdx.x * blockDim.x + threadIdx.x) >> 5;
    int lane = threadIdx.x & 31;
    if (warp >= n_nh) return;
    int hh = warp % Hh;
    const float* hp  = h + (size_t)warp * Cc;
    const float* asp = a_s + hh * Cc;
    const float* adp = a_d + hh * Cc;
    float s = 0.f, d = 0.f;
    for (int c = lane; c < Cc; c += 32) {
        float v = hp[c];
        s += v * asp[c];
        d += v * adp[c];
    }
    #pragma unroll
    for (int o = 16; o > 0; o >>= 1) {
        s += __shfl_xor_sync(0xFFFFFFFFu, s, o);
        d += __shfl_xor_sync(0xFFFFFFFFu, d, o);
    }
    if (lane == 0) { as_out[warp] = s; ad_out[warp] = d; }
}

// ---------------- edge pass 1: e = leaky_relu(..); segment max ---------------
__global__ void k_edge_max(const int* __restrict__ ei,
                           const float* __restrict__ as, const float* __restrict__ ad,
                           float* __restrict__ e_out, unsigned* __restrict__ m, int Hh)
{
    int idx = blockIdx.x * blockDim.x + threadIdx.x;
    int tot = EP * Hh;
    if (idx >= tot) return;
    int e = idx / Hh, hh = idx - e * Hh;
    int s, dn;
    if (e < EE) { s = ei[e]; dn = ei[EE + e]; }
    else        { s = e - EE; dn = s; }
    float v = as[s * Hh + hh] + ad[dn * Hh + hh];
    v = (v > 0.f) ? v : NEG_SLOPE * v;
    e_out[idx] = v;
    atomicMax(&m[dn * Hh + hh], fenc(v));
}

// ---------------- edge pass 2: ex = exp(e - m[dst]); segment sum -------------
__global__ void k_edge_exp(const int* __restrict__ ei,
                           float* __restrict__ e_buf,
                           const unsigned* __restrict__ m, float* __restrict__ denom, int Hh)
{
    int idx = blockIdx.x * blockDim.x + threadIdx.x;
    int tot = EP * Hh;
    if (idx >= tot) return;
    int e = idx / Hh, hh = idx - e * Hh;
    int dn;
    if (e < EE) dn = ei[EE + e];
    else        dn = e - EE;
    float mx = fdec(m[dn * Hh + hh]);
    float ex = __expf(e_buf[idx] - mx);
    e_buf[idx] = ex;
    atomicAdd(&denom[dn * Hh + hh], ex);
}

// ---------------- reciprocal of denominators ---------------------------------
__global__ void k_rcp(float* __restrict__ d, int n) {
    int i = blockIdx.x * blockDim.x + threadIdx.x;
    if (i < n) d[i] = 1.0f / d[i];
}

// ---------------- aggregation layer 1: out[dst] += alpha * h[src], 256 ch ----
__global__ void k_agg1(const int* __restrict__ ei,
                       const float* __restrict__ e_buf, const float* __restrict__ dinv,
                       const float* __restrict__ h, float* __restrict__ out)
{
    long long idx = (long long)blockIdx.x * blockDim.x + threadIdx.x;
    if (idx >= (long long)EP * 64) return;
    int e = (int)(idx >> 6), q = (int)(idx & 63);
    int s, dn;
    if (e < EE) { s = ei[e]; dn = ei[EE + e]; }
    else        { s = e - EE; dn = s; }
    int hh = q >> 4;
    float a = e_buf[e * 4 + hh] * dinv[dn * 4 + hh];
    float4 hv = *(const float4*)(h + (size_t)s * HC1 + q * 4);
    red_add_v4(out + (size_t)dn * HC1 + q * 4,
               make_float4(a * hv.x, a * hv.y, a * hv.z, a * hv.w));
}

// ---------------- aggregation layer 2: 64 ch, 1 head -------------------------
__global__ void k_agg2(const int* __restrict__ ei,
                       const float* __restrict__ e_buf, const float* __restrict__ dinv,
                       const float* __restrict__ h, float* __restrict__ out)
{
    long long idx = (long long)blockIdx.x * blockDim.x + threadIdx.x;
    if (idx >= (long long)EP * 16) return;
    int e = (int)(idx >> 4), q = (int)(idx & 15);
    int s, dn;
    if (e < EE) { s = ei[e]; dn = ei[EE + e]; }
    else        { s = e - EE; dn = s; }
    float a = e_buf[e] * dinv[dn];
    float4 hv = *(const float4*)(h + (size_t)s * OC + q * 4);
    red_add_v4(out + (size_t)dn * OC + q * 4,
               make_float4(a * hv.x, a * hv.y, a * hv.z, a * hv.w));
}

// ---------------- elu(out1 + b1) -> x2 ---------------------------------------
__global__ void k_elu_bias(const float* __restrict__ in, const float* __restrict__ b,
                           float* __restrict__ out, int total4, int cols4)
{
    int i = blockIdx.x * blockDim.x + threadIdx.x;
    if (i >= total4) return;
    float4 v = ((const float4*)in)[i];
    float4 bb = ((const float4*)b)[i % cols4];
    v.x += bb.x; v.y += bb.y; v.z += bb.z; v.w += bb.w;
    v.x = (v.x > 0.f) ? v.x : expm1f(v.x);
    v.y = (v.y > 0.f) ? v.y : expm1f(v.y);
    v.z = (v.z > 0.f) ? v.z : expm1f(v.z);
    v.w = (v.w > 0.f) ? v.w : expm1f(v.w);
    ((float4*)out)[i] = v;
}

// ---------------- final bias add ---------------------------------------------
__global__ void k_bias(float* __restrict__ out, const float* __restrict__ b,
                       int total, int cols)
{
    int i = blockIdx.x * blockDim.x + threadIdx.x;
    if (i >= total) return;
    out[i] += b[i % cols];
}

// =============================================================================
extern "C" void kernel_launch(void* const* d_in, const int* in_sizes, int n_in,
                              void* d_out, int out_size)
{
    const float* x     = (const float*)d_in[0];
    const int*   ei    = (const int*)d_in[1];
    const float* W1    = (const float*)d_in[2];
    const float* a_s1  = (const float*)d_in[3];
    const float* a_d1  = (const float*)d_in[4];
    const float* b1    = (const float*)d_in[5];
    const float* W2    = (const float*)d_in[6];
    const float* a_s2  = (const float*)d_in[7];
    const float* a_d2  = (const float*)d_in[8];
    const float* b2    = (const float*)d_in[9];
    float*       out   = (float*)d_out;

    float *h1, *out1, *as1, *ad1, *e1, *d1, *h2, *as2, *ad2, *e2, *d2;
    unsigned *m1, *m2;
    cudaGetSymbolAddress((void**)&h1,   g_h1);
    cudaGetSymbolAddress((void**)&out1, g_out1);
    cudaGetSymbolAddress((void**)&as1,  g_as1);
    cudaGetSymbolAddress((void**)&ad1,  g_ad1);
    cudaGetSymbolAddress((void**)&e1,   g_e1);
    cudaGetSymbolAddress((void**)&m1,   g_m1);
    cudaGetSymbolAddress((void**)&d1,   g_d1);
    cudaGetSymbolAddress((void**)&h2,   g_h2);
    cudaGetSymbolAddress((void**)&as2,  g_as2);
    cudaGetSymbolAddress((void**)&ad2,  g_ad2);
    cudaGetSymbolAddress((void**)&e2,   g_e2);
    cudaGetSymbolAddress((void**)&m2,   g_m2);
    cudaGetSymbolAddress((void**)&d2,   g_d2);

    k_init<<<2048, 256>>>(out);

    // ---- layer 1 ----
    {
        dim3 grid((HC1 + GBN - 1) / GBN, (NN + GBM - 1) / GBM);
        k_sgemm128<<<grid, 256>>>(x, W1, h1, NN, HC1, INC);
    }
    {
        int warps = NN * H1;
        k_alpha<<<(warps * 32 + 255) / 256, 256>>>(h1, a_s1, a_d1, as1, ad1, warps, H1, C1);
    }
    {
        int tot = EP * H1;
        int blk = (tot + 255) / 256;
        k_edge_max<<<blk, 256>>>(ei, as1, ad1, e1, m1, H1);
        k_edge_exp<<<blk, 256>>>(ei, e1, m1, d1, H1);
        k_rcp<<<(NN * H1 + 255) / 256, 256>>>(d1, NN * H1);
    }
    {
        long long tot = (long long)EP * 64;
        int blk = (int)((tot + 255) / 256);
        k_agg1<<<blk, 256>>>(ei, e1, d1, h1, out1);
    }
    {
        int tot4 = NN * HC1 / 4;
        k_elu_bias<<<(tot4 + 255) / 256, 256>>>(out1, b1, h1, tot4, HC1 / 4);
    }

    // ---- layer 2 ----
    {
        dim3 grid((OC + GBN - 1) / GBN, (NN + GBM - 1) / GBM);
        k_sgemm128<<<grid, 256>>>(h1, W2, h2, NN, OC, HC1);
    }
    {
        int warps = NN;
        k_alpha<<<(warps * 32 + 255) / 256, 256>>>(h2, a_s2, a_d2, as2, ad2, warps, 1, OC);
    }
    {
        int tot = EP;
        int blk = (tot + 255) / 256;
        k_edge_max<<<blk, 256>>>(ei, as2, ad2, e2, m2, 1);
        k_edge_exp<<<blk, 256>>>(ei, e2, m2, d2, 1);
        k_rcp<<<(NN + 255) / 256, 256>>>(d2, NN);
    }
    {
        long long tot = (long long)EP * 16;
        int blk = (int)((tot + 255) / 256);
        k_agg2<<<blk, 256>>>(ei, e2, d2, h2, out);
    }
    {
        int tot = NN * OC;
        k_bias<<<(tot + 255) / 256, 256>>>(out, b2, tot, OC);
    }
}

// round 4
// speedup vs baseline: 3.0679x; 1.6014x over previous
#include <cuda_runtime.h>
#include <cuda_bf16.h>
#include <math.h>

// ---------------- problem constants ----------------
#define NN    50000
#define EE    800000
#define EP    850000          // EE + NN self loops
#define INC   1024
#define H1    4
#define C1    64
#define HC1   256             // H1*C1
#define OC    64
#define NEG_SLOPE 0.2f

// ---------------- scratch (device globals) ----------------
__device__ float    g_h1[(size_t)NN * HC1];
__device__ float    g_out1[(size_t)NN * HC1];
__device__ float    g_as1[NN * H1];
__device__ float    g_ad1[NN * H1];
__device__ float    g_e1[(size_t)EP * H1];
__device__ unsigned g_m1[NN * H1];
__device__ float    g_d1[NN * H1];

__device__ float    g_h2[(size_t)NN * OC];
__device__ float    g_as2[NN];
__device__ float    g_ad2[NN];
__device__ float    g_e2[EP];
__device__ unsigned g_m2[NN];
__device__ float    g_d2[NN];

// monotonic float<->uint encoding for atomicMax on floats
__device__ __forceinline__ unsigned fenc(float f) {
    unsigned u = __float_as_uint(f);
    return (u & 0x80000000u) ? ~u : (u | 0x80000000u);
}
__device__ __forceinline__ float fdec(unsigned e) {
    unsigned u = (e & 0x80000000u) ? (e ^ 0x80000000u) : ~e;
    return __uint_as_float(u);
}
#define ENC_NEG_INF 0x007FFFFFu   // fenc(-inf)

__device__ __forceinline__ void red_add_v4(float* p, float4 v) {
    asm volatile("red.global.add.v4.f32 [%0], {%1,%2,%3,%4};"
                 :: "l"(p), "f"(v.x), "f"(v.y), "f"(v.z), "f"(v.w) : "memory");
}

__device__ __forceinline__ unsigned f2tf32(float f) {
    unsigned r;
    asm("cvt.rna.tf32.f32 %0, %1;" : "=r"(r) : "f"(f));
    return r;
}

// ---------------- init ----------------
__global__ void k_init(float* dout) {
    int i = blockIdx.x * blockDim.x + threadIdx.x;
    int stride = gridDim.x * blockDim.x;
    float4 z = make_float4(0.f, 0.f, 0.f, 0.f);
    for (int j = i; j < NN * HC1 / 4; j += stride) ((float4*)g_out1)[j] = z;
    for (int j = i; j < NN * H1;  j += stride) { g_m1[j] = ENC_NEG_INF; g_d1[j] = 0.f; }
    for (int j = i; j < NN;       j += stride) { g_m2[j] = ENC_NEG_INF; g_d2[j] = 0.f; }
    for (int j = i; j < NN * OC / 4; j += stride) ((float4*)dout)[j] = z;
}

// ============= TF32 tensor-core GEMM: C[m,n] = sum_k A[m,k]*B[n,k] ===========
// 128x128x32 block tile, 8 warps (2x4), each warp 64x32 via m16n8k8 mma.
#define TBM 128
#define TBN 128
#define TBK 32
#define TSS 36   // padded smem row stride (u32 words)

__global__ __launch_bounds__(256) void k_tf32gemm(
    const float* __restrict__ A, const float* __restrict__ B,
    float* __restrict__ C, int M, int N, int K)
{
    __shared__ unsigned As[TBM][TSS];
    __shared__ unsigned Bs[TBN][TSS];

    int tid = threadIdx.x;
    int bm = blockIdx.y * TBM, bn = blockIdx.x * TBN;
    int wid = tid >> 5, lane = tid & 31;
    int wm = (wid >> 2) * 64;        // 0 / 64
    int wn = (wid & 3) * 32;         // 0 / 32 / 64 / 96
    int g  = lane >> 2;              // 0..7
    int t4 = lane & 3;               // 0..3

    // global load mapping: each thread: 4 rows (r0 + 32*i), 4 consecutive cols
    int r0 = tid >> 3;               // 0..31
    int c4 = (tid & 7) * 4;          // 0,4,...,28

    float c[4][4][4];
    #pragma unroll
    for (int i = 0; i < 4; i++)
        #pragma unroll
        for (int j = 0; j < 4; j++)
            #pragma unroll
            for (int r = 0; r < 4; r++) c[i][j][r] = 0.f;

    const float4 zero4 = make_float4(0.f, 0.f, 0.f, 0.f);
    float4 pa[4], pb[4];
    int nt = K / TBK;

    // prologue: fetch tile 0
    #pragma unroll
    for (int i = 0; i < 4; i++) {
        int ar = bm + r0 + 32 * i;
        pa[i] = (ar < M) ? *(const float4*)(A + (size_t)ar * K + c4) : zero4;
        int br = bn + r0 + 32 * i;
        pb[i] = (br < N) ? *(const float4*)(B + (size_t)br * K + c4) : zero4;
    }
    #pragma unroll
    for (int i = 0; i < 4; i++) {
        int rr = r0 + 32 * i;
        As[rr][c4 + 0] = f2tf32(pa[i].x); As[rr][c4 + 1] = f2tf32(pa[i].y);
        As[rr][c4 + 2] = f2tf32(pa[i].z); As[rr][c4 + 3] = f2tf32(pa[i].w);
        Bs[rr][c4 + 0] = f2tf32(pb[i].x); Bs[rr][c4 + 1] = f2tf32(pb[i].y);
        Bs[rr][c4 + 2] = f2tf32(pb[i].z); Bs[rr][c4 + 3] = f2tf32(pb[i].w);
    }
    __syncthreads();

    for (int t = 0; t < nt; t++) {
        bool more = (t + 1 < nt);
        if (more) {
            int k0 = (t + 1) * TBK;
            #pragma unroll
            for (int i = 0; i < 4; i++) {
                int ar = bm + r0 + 32 * i;
                pa[i] = (ar < M) ? *(const float4*)(A + (size_t)ar * K + k0 + c4) : zero4;
                int br = bn + r0 + 32 * i;
                pb[i] = (br < N) ? *(const float4*)(B + (size_t)br * K + k0 + c4) : zero4;
            }
        }
        // compute on current smem tile
        #pragma unroll
        for (int ks = 0; ks < 4; ks++) {
            int k8 = ks * 8;
            unsigned af[4][4], bf[4][2];
            #pragma unroll
            for (int mt = 0; mt < 4; mt++) {
                int row = wm + mt * 16 + g;
                af[mt][0] = As[row][k8 + t4];
                af[mt][1] = As[row + 8][k8 + t4];
                af[mt][2] = As[row][k8 + t4 + 4];
                af[mt][3] = As[row + 8][k8 + t4 + 4];
            }
            #pragma unroll
            for (int ntj = 0; ntj < 4; ntj++) {
                int col = wn + ntj * 8 + g;
                bf[ntj][0] = Bs[col][k8 + t4];
                bf[ntj][1] = Bs[col][k8 + t4 + 4];
            }
            #pragma unroll
            for (int mt = 0; mt < 4; mt++)
                #pragma unroll
                for (int ntj = 0; ntj < 4; ntj++) {
                    asm volatile(
                        "mma.sync.aligned.m16n8k8.row.col.f32.tf32.tf32.f32 "
                        "{%0,%1,%2,%3}, {%4,%5,%6,%7}, {%8,%9}, {%0,%1,%2,%3};"
                        : "+f"(c[mt][ntj][0]), "+f"(c[mt][ntj][1]),
                          "+f"(c[mt][ntj][2]), "+f"(c[mt][ntj][3])
                        : "r"(af[mt][0]), "r"(af[mt][1]), "r"(af[mt][2]), "r"(af[mt][3]),
                          "r"(bf[ntj][0]), "r"(bf[ntj][1]));
                }
        }
        if (more) {
            __syncthreads();
            #pragma unroll
            for (int i = 0; i < 4; i++) {
                int rr = r0 + 32 * i;
                As[rr][c4 + 0] = f2tf32(pa[i].x); As[rr][c4 + 1] = f2tf32(pa[i].y);
                As[rr][c4 + 2] = f2tf32(pa[i].z); As[rr][c4 + 3] = f2tf32(pa[i].w);
                Bs[rr][c4 + 0] = f2tf32(pb[i].x); Bs[rr][c4 + 1] = f2tf32(pb[i].y);
                Bs[rr][c4 + 2] = f2tf32(pb[i].z); Bs[rr][c4 + 3] = f2tf32(pb[i].w);
            }
            __syncthreads();
        }
    }

    // epilogue
    #pragma unroll
    for (int mt = 0; mt < 4; mt++) {
        int row0 = bm + wm + mt * 16 + g;
        #pragma unroll
        for (int ntj = 0; ntj < 4; ntj++) {
            int col = bn + wn + ntj * 8 + t4 * 2;
            if (row0 < M && col + 1 < N) {
                C[(size_t)row0 * N + col]     = c[mt][ntj][0];
                C[(size_t)row0 * N + col + 1] = c[mt][ntj][1];
            }
            if (row0 + 8 < M && col + 1 < N) {
                C[(size_t)(row0 + 8) * N + col]     = c[mt][ntj][2];
                C[(size_t)(row0 + 8) * N + col + 1] = c[mt][ntj][3];
            }
        }
    }
}

// ---------------- fp32 SGEMM (layer 2; small) --------------------------------
#define GBM 128
#define GBN 128
#define GBK 8
#define SAS 132

__global__ __launch_bounds__(256) void k_sgemm128(
    const float* __restrict__ A, const float* __restrict__ B,
    float* __restrict__ C, int M, int N, int K)
{
    __shared__ float As[2][GBK][SAS];
    __shared__ float Bs[2][GBK][SAS];
    int tid = threadIdx.x;
    int bm = blockIdx.y * GBM, bn = blockIdx.x * GBN;
    int lr = tid >> 1;
    int lk = (tid & 1) * 4;
    int tx = tid & 15, ty = tid >> 4;
    int tx4 = tx * 4, ty4 = ty * 4;
    float c[8][8] = {};
    int nt = K / GBK;
    float4 ra, rb;
    const float4 zero4 = make_float4(0.f, 0.f, 0.f, 0.f);
    {
        int gm = bm + lr;
        ra = (gm < M) ? *(const float4*)(A + (size_t)gm * K + lk) : zero4;
        int gn = bn + lr;
        rb = (gn < N) ? *(const float4*)(B + (size_t)gn * K + lk) : zero4;
        As[0][lk + 0][lr] = ra.x; As[0][lk + 1][lr] = ra.y;
        As[0][lk + 2][lr] = ra.z; As[0][lk + 3][lr] = ra.w;
        Bs[0][lk + 0][lr] = rb.x; Bs[0][lk + 1][lr] = rb.y;
        Bs[0][lk + 2][lr] = rb.z; Bs[0][lk + 3][lr] = rb.w;
    }
    __syncthreads();
    int cur = 0;
    for (int t = 0; t < nt; t++) {
        bool more = (t + 1 < nt);
        if (more) {
            int k0n = (t + 1) * GBK;
            int gm = bm + lr;
            ra = (gm < M) ? *(const float4*)(A + (size_t)gm * K + k0n + lk) : zero4;
            int gn = bn + lr;
            rb = (gn < N) ? *(const float4*)(B + (size_t)gn * K + k0n + lk) : zero4;
        }
        #pragma unroll
        for (int k = 0; k < GBK; k++) {
            float4 a0 = *(const float4*)&As[cur][k][ty4];
            float4 a1 = *(const float4*)&As[cur][k][ty4 + 64];
            float4 b0 = *(const float4*)&Bs[cur][k][tx4];
            float4 b1 = *(const float4*)&Bs[cur][k][tx4 + 64];
            float av[8] = {a0.x, a0.y, a0.z, a0.w, a1.x, a1.y, a1.z, a1.w};
            float bv[8] = {b0.x, b0.y, b0.z, b0.w, b1.x, b1.y, b1.z, b1.w};
            #pragma unroll
            for (int i = 0; i < 8; i++)
                #pragma unroll
                for (int j = 0; j < 8; j++) c[i][j] += av[i] * bv[j];
        }
        if (more) {
            int nx = cur ^ 1;
            As[nx][lk + 0][lr] = ra.x; As[nx][lk + 1][lr] = ra.y;
            As[nx][lk + 2][lr] = ra.z; As[nx][lk + 3][lr] = ra.w;
            Bs[nx][lk + 0][lr] = rb.x; Bs[nx][lk + 1][lr] = rb.y;
            Bs[nx][lk + 2][lr] = rb.z; Bs[nx][lk + 3][lr] = rb.w;
            __syncthreads();
            cur = nx;
        }
    }
    #pragma unroll
    for (int i = 0; i < 8; i++) {
        int gm = bm + ((i < 4) ? (ty4 + i) : (60 + ty4 + i));
        if (gm >= M) continue;
        int gn0 = bn + tx4;
        if (gn0 + 3 < N)
            *(float4*)&C[(size_t)gm * N + gn0] =
                make_float4(c[i][0], c[i][1], c[i][2], c[i][3]);
        int gn1 = bn + 64 + tx4;
        if (gn1 + 3 < N)
            *(float4*)&C[(size_t)gm * N + gn1] =
                make_float4(c[i][4], c[i][5], c[i][6], c[i][7]);
    }
}

// ---------------- per-(node,head) attention coefficients ---------------------
__global__ void k_alpha(const float* __restrict__ h,
                        const float* __restrict__ a_s, const float* __restrict__ a_d,
                        float* __restrict__ as_out, float* __restrict__ ad_out,
                        int n_nh, int Hh, int Cc)
{
    int warp = (blockIdx.x * blockDim.x + threadIdx.x) >> 5;
    int lane = threadIdx.x & 31;
    if (warp >= n_nh) return;
    int hh = warp % Hh;
    const float* hp  = h + (size_t)warp * Cc;
    const float* asp = a_s + hh * Cc;
    const float* adp = a_d + hh * Cc;
    float s = 0.f, d = 0.f;
    for (int c = lane; c < Cc; c += 32) {
        float v = hp[c];
        s += v * asp[c];
        d += v * adp[c];
    }
    #pragma unroll
    for (int o = 16; o > 0; o >>= 1) {
        s += __shfl_xor_sync(0xFFFFFFFFu, s, o);
        d += __shfl_xor_sync(0xFFFFFFFFu, d, o);
    }
    if (lane == 0) { as_out[warp] = s; ad_out[warp] = d; }
}

// ---------------- edge passes ------------------------------------------------
__global__ void k_edge_max(const int* __restrict__ ei,
                           const float* __restrict__ as, const float* __restrict__ ad,
                           float* __restrict__ e_out, unsigned* __restrict__ m, int Hh)
{
    int idx = blockIdx.x * blockDim.x + threadIdx.x;
    int tot = EP * Hh;
    if (idx >= tot) return;
    int e = idx / Hh, hh = idx - e * Hh;
    int s, dn;
    if (e < EE) { s = ei[e]; dn = ei[EE + e]; }
    else        { s = e - EE; dn = s; }
    float v = as[s * Hh + hh] + ad[dn * Hh + hh];
    v = (v > 0.f) ? v : NEG_SLOPE * v;
    e_out[idx] = v;
    atomicMax(&m[dn * Hh + hh], fenc(v));
}

__global__ void k_edge_exp(const int* __restrict__ ei,
                           float* __restrict__ e_buf,
                           const unsigned* __restrict__ m, float* __restrict__ denom, int Hh)
{
    int idx = blockIdx.x * blockDim.x + threadIdx.x;
    int tot = EP * Hh;
    if (idx >= tot) return;
    int e = idx / Hh, hh = idx - e * Hh;
    int dn;
    if (e < EE) dn = ei[EE + e];
    else        dn = e - EE;
    float mx = fdec(m[dn * Hh + hh]);
    float ex = __expf(e_buf[idx] - mx);
    e_buf[idx] = ex;
    atomicAdd(&denom[dn * Hh + hh], ex);
}

__global__ void k_rcp(float* __restrict__ d, int n) {
    int i = blockIdx.x * blockDim.x + threadIdx.x;
    if (i < n) d[i] = 1.0f / d[i];
}

// ---------------- aggregation ------------------------------------------------
__global__ void k_agg1(const int* __restrict__ ei,
                       const float* __restrict__ e_buf, const float* __restrict__ dinv,
                       const float* __restrict__ h, float* __restrict__ out)
{
    long long idx = (long long)blockIdx.x * blockDim.x + threadIdx.x;
    if (idx >= (long long)EP * 64) return;
    int e = (int)(idx >> 6), q = (int)(idx & 63);
    int s, dn;
    if (e < EE) { s = ei[e]; dn = ei[EE + e]; }
    else        { s = e - EE; dn = s; }
    int hh = q >> 4;
    float a = e_buf[e * 4 + hh] * dinv[dn * 4 + hh];
    float4 hv = *(const float4*)(h + (size_t)s * HC1 + q * 4);
    red_add_v4(out + (size_t)dn * HC1 + q * 4,
               make_float4(a * hv.x, a * hv.y, a * hv.z, a * hv.w));
}

__global__ void k_agg2(const int* __restrict__ ei,
                       const float* __restrict__ e_buf, const float* __restrict__ dinv,
                       const float* __restrict__ h, float* __restrict__ out)
{
    long long idx = (long long)blockIdx.x * blockDim.x + threadIdx.x;
    if (idx >= (long long)EP * 16) return;
    int e = (int)(idx >> 4), q = (int)(idx & 15);
    int s, dn;
    if (e < EE) { s = ei[e]; dn = ei[EE + e]; }
    else        { s = e - EE; dn = s; }
    float a = e_buf[e] * dinv[dn];
    float4 hv = *(const float4*)(h + (size_t)s * OC + q * 4);
    red_add_v4(out + (size_t)dn * OC + q * 4,
               make_float4(a * hv.x, a * hv.y, a * hv.z, a * hv.w));
}

// ---------------- elu / bias -------------------------------------------------
__global__ void k_elu_bias(const float* __restrict__ in, const float* __restrict__ b,
                           float* __restrict__ out, int total4, int cols4)
{
    int i = blockIdx.x * blockDim.x + threadIdx.x;
    if (i >= total4) return;
    float4 v = ((const float4*)in)[i];
    float4 bb = ((const float4*)b)[i % cols4];
    v.x += bb.x; v.y += bb.y; v.z += bb.z; v.w += bb.w;
    v.x = (v.x > 0.f) ? v.x : expm1f(v.x);
    v.y = (v.y > 0.f) ? v.y : expm1f(v.y);
    v.z = (v.z > 0.f) ? v.z : expm1f(v.z);
    v.w = (v.w > 0.f) ? v.w : expm1f(v.w);
    ((float4*)out)[i] = v;
}

__global__ void k_bias(float* __restrict__ out, const float* __restrict__ b,
                       int total, int cols)
{
    int i = blockIdx.x * blockDim.x + threadIdx.x;
    if (i >= total) return;
    out[i] += b[i % cols];
}

// =============================================================================
extern "C" void kernel_launch(void* const* d_in, const int* in_sizes, int n_in,
                              void* d_out, int out_size)
{
    const float* x     = (const float*)d_in[0];
    const int*   ei    = (const int*)d_in[1];
    const float* W1    = (const float*)d_in[2];
    const float* a_s1  = (const float*)d_in[3];
    const float* a_d1  = (const float*)d_in[4];
    const float* b1    = (const float*)d_in[5];
    const float* W2    = (const float*)d_in[6];
    const float* a_s2  = (const float*)d_in[7];
    const float* a_d2  = (const float*)d_in[8];
    const float* b2    = (const float*)d_in[9];
    float*       out   = (float*)d_out;

    float *h1, *out1, *as1, *ad1, *e1, *d1, *h2, *as2, *ad2, *e2, *d2;
    unsigned *m1, *m2;
    cudaGetSymbolAddress((void**)&h1,   g_h1);
    cudaGetSymbolAddress((void**)&out1, g_out1);
    cudaGetSymbolAddress((void**)&as1,  g_as1);
    cudaGetSymbolAddress((void**)&ad1,  g_ad1);
    cudaGetSymbolAddress((void**)&e1,   g_e1);
    cudaGetSymbolAddress((void**)&m1,   g_m1);
    cudaGetSymbolAddress((void**)&d1,   g_d1);
    cudaGetSymbolAddress((void**)&h2,   g_h2);
    cudaGetSymbolAddress((void**)&as2,  g_as2);
    cudaGetSymbolAddress((void**)&ad2,  g_ad2);
    cudaGetSymbolAddress((void**)&e2,   g_e2);
    cudaGetSymbolAddress((void**)&m2,   g_m2);
    cudaGetSymbolAddress((void**)&d2,   g_d2);

    k_init<<<2048, 256>>>(out);

    // ---- layer 1 ----
    {
        dim3 grid((HC1 + TBN - 1) / TBN, (NN + TBM - 1) / TBM);
        k_tf32gemm<<<grid, 256>>>(x, W1, h1, NN, HC1, INC);
    }
    {
        int warps = NN * H1;
        k_alpha<<<(warps * 32 + 255) / 256, 256>>>(h1, a_s1, a_d1, as1, ad1, warps, H1, C1);
    }
    {
        int tot = EP * H1;
        int blk = (tot + 255) / 256;
        k_edge_max<<<blk, 256>>>(ei, as1, ad1, e1, m1, H1);
        k_edge_exp<<<blk, 256>>>(ei, e1, m1, d1, H1);
        k_rcp<<<(NN * H1 + 255) / 256, 256>>>(d1, NN * H1);
    }
    {
        long long tot = (long long)EP * 64;
        int blk = (int)((tot + 255) / 256);
        k_agg1<<<blk, 256>>>(ei, e1, d1, h1, out1);
    }
    {
        int tot4 = NN * HC1 / 4;
        k_elu_bias<<<(tot4 + 255) / 256, 256>>>(out1, b1, h1, tot4, HC1 / 4);
    }

    // ---- layer 2 ----
    {
        dim3 grid((OC + GBN - 1) / GBN, (NN + GBM - 1) / GBM);
        k_sgemm128<<<grid, 256>>>(h1, W2, h2, NN, OC, HC1);
    }
    {
        int warps = NN;
        k_alpha<<<(warps * 32 + 255) / 256, 256>>>(h2, a_s2, a_d2, as2, ad2, warps, 1, OC);
    }
    {
        int tot = EP;
        int blk = (tot + 255) / 256;
        k_edge_max<<<blk, 256>>>(ei, as2, ad2, e2, m2, 1);
        k_edge_exp<<<blk, 256>>>(ei, e2, m2, d2, 1);
        k_rcp<<<(NN + 255) / 256, 256>>>(d2, NN);
    }
    {
        long long tot = (long long)EP * 16;
        int blk = (int)((tot + 255) / 256);
        k_agg2<<<blk, 256>>>(ei, e2, d2, h2, out);
    }
    {
        int tot = NN * OC;
        k_bias<<<(tot + 255) / 256, 256>>>(out, b2, tot, OC);
    }
}

// round 5
// speedup vs baseline: 4.6232x; 1.5069x over previous
#include <cuda_runtime.h>
#include <cuda_bf16.h>
#include <math.h>

// ---------------- problem constants ----------------
#define NN    50000
#define EE    800000
#define EP    850000          // EE + NN self loops
#define INC   1024
#define H1    4
#define C1    64
#define HC1   256             // H1*C1
#define OC    64
#define NEG_SLOPE 0.2f

#define SCAN_T 512
#define NTILES ((NN + SCAN_T - 1) / SCAN_T)

// ---------------- scratch (device globals) ----------------
__device__ float  g_h1[(size_t)NN * HC1];     // layer1 projected features
__device__ float  g_x2[(size_t)NN * HC1];     // elu(agg1 + b1)
__device__ float  g_as1[NN * H1];
__device__ float  g_ad1[NN * H1];
__device__ float4 g_alpha1[EP];               // per-edge alpha (4 heads), CSR order

__device__ float  g_h2[(size_t)NN * OC];
__device__ float  g_as2[NN];
__device__ float  g_ad2[NN];
__device__ float  g_alpha2[EP];

// CSR
__device__ int g_deg[NN];
__device__ int g_rowptr[NN + 1];
__device__ int g_cursor[NN];
__device__ int g_srcidx[EP];
__device__ int g_bsum[NTILES];

__device__ __forceinline__ unsigned f2tf32(float f) {
    unsigned r;
    asm("cvt.rna.tf32.f32 %0, %1;" : "=r"(r) : "f"(f));
    return r;
}

// ================= CSR construction =================
__global__ void k_zero_deg() {
    int i = blockIdx.x * blockDim.x + threadIdx.x;
    if (i < NN) g_deg[i] = 0;
}
__global__ void k_count(const int* __restrict__ ei) {
    int e = blockIdx.x * blockDim.x + threadIdx.x;
    if (e >= EP) return;
    int dn = (e < EE) ? ei[EE + e] : (e - EE);
    atomicAdd(&g_deg[dn], 1);
}
__global__ __launch_bounds__(SCAN_T) void k_scan1() {
    __shared__ int s[SCAN_T];
    int tid = threadIdx.x;
    int i = blockIdx.x * SCAN_T + tid;
    int v = (i < NN) ? g_deg[i] : 0;
    s[tid] = v;
    __syncthreads();
    #pragma unroll
    for (int off = 1; off < SCAN_T; off <<= 1) {
        int t = (tid >= off) ? s[tid - off] : 0;
        __syncthreads();
        s[tid] += t;
        __syncthreads();
    }
    if (i < NN) g_rowptr[i + 1] = s[tid];
    if (tid == SCAN_T - 1) g_bsum[blockIdx.x] = s[tid];
}
__global__ void k_scan2() {
    if (threadIdx.x == 0) {
        int run = 0;
        for (int t = 0; t < NTILES; t++) { int v = g_bsum[t]; g_bsum[t] = run; run += v; }
        g_rowptr[0] = 0;
    }
}
__global__ __launch_bounds__(SCAN_T) void k_scan3() {
    int i = blockIdx.x * SCAN_T + threadIdx.x;
    if (i < NN) {
        int r = g_rowptr[i + 1] + g_bsum[blockIdx.x];
        g_rowptr[i + 1] = r;
        // also init cursor for the scatter (cursor[i] = rowptr[i])
    }
}
__global__ void k_setcur() {
    int i = blockIdx.x * blockDim.x + threadIdx.x;
    if (i < NN) g_cursor[i] = g_rowptr[i];
}
__global__ void k_scatter(const int* __restrict__ ei) {
    int e = blockIdx.x * blockDim.x + threadIdx.x;
    if (e >= EP) return;
    int s, dn;
    if (e < EE) { s = ei[e]; dn = ei[EE + e]; }
    else        { s = e - EE; dn = s; }
    int pos = atomicAdd(&g_cursor[dn], 1);
    g_srcidx[pos] = s;
}

// ============= TF32 tensor-core GEMM: C[m,n] = sum_k A[m,k]*B[n,k] ===========
#define TBM 128
#define TBN 128
#define TBK 32
#define TSS 36

__global__ __launch_bounds__(256) void k_tf32gemm(
    const float* __restrict__ A, const float* __restrict__ B,
    float* __restrict__ C, int M, int N, int K)
{
    __shared__ unsigned As[TBM][TSS];
    __shared__ unsigned Bs[TBN][TSS];

    int tid = threadIdx.x;
    int bm = blockIdx.y * TBM, bn = blockIdx.x * TBN;
    int wid = tid >> 5, lane = tid & 31;
    int wm = (wid >> 2) * 64;
    int wn = (wid & 3) * 32;
    int g  = lane >> 2;
    int t4 = lane & 3;

    int r0 = tid >> 3;
    int c4 = (tid & 7) * 4;

    float c[4][4][4];
    #pragma unroll
    for (int i = 0; i < 4; i++)
        #pragma unroll
        for (int j = 0; j < 4; j++)
            #pragma unroll
            for (int r = 0; r < 4; r++) c[i][j][r] = 0.f;

    const float4 zero4 = make_float4(0.f, 0.f, 0.f, 0.f);
    float4 pa[4], pb[4];
    int nt = K / TBK;

    #pragma unroll
    for (int i = 0; i < 4; i++) {
        int ar = bm + r0 + 32 * i;
        pa[i] = (ar < M) ? *(const float4*)(A + (size_t)ar * K + c4) : zero4;
        int br = bn + r0 + 32 * i;
        pb[i] = (br < N) ? *(const float4*)(B + (size_t)br * K + c4) : zero4;
    }
    #pragma unroll
    for (int i = 0; i < 4; i++) {
        int rr = r0 + 32 * i;
        As[rr][c4 + 0] = f2tf32(pa[i].x); As[rr][c4 + 1] = f2tf32(pa[i].y);
        As[rr][c4 + 2] = f2tf32(pa[i].z); As[rr][c4 + 3] = f2tf32(pa[i].w);
        Bs[rr][c4 + 0] = f2tf32(pb[i].x); Bs[rr][c4 + 1] = f2tf32(pb[i].y);
        Bs[rr][c4 + 2] = f2tf32(pb[i].z); Bs[rr][c4 + 3] = f2tf32(pb[i].w);
    }
    __syncthreads();

    for (int t = 0; t < nt; t++) {
        bool more = (t + 1 < nt);
        if (more) {
            int k0 = (t + 1) * TBK;
            #pragma unroll
            for (int i = 0; i < 4; i++) {
                int ar = bm + r0 + 32 * i;
                pa[i] = (ar < M) ? *(const float4*)(A + (size_t)ar * K + k0 + c4) : zero4;
                int br = bn + r0 + 32 * i;
                pb[i] = (br < N) ? *(const float4*)(B + (size_t)br * K + k0 + c4) : zero4;
            }
        }
        #pragma unroll
        for (int ks = 0; ks < 4; ks++) {
            int k8 = ks * 8;
            unsigned af[4][4], bf[4][2];
            #pragma unroll
            for (int mt = 0; mt < 4; mt++) {
                int row = wm + mt * 16 + g;
                af[mt][0] = As[row][k8 + t4];
                af[mt][1] = As[row + 8][k8 + t4];
                af[mt][2] = As[row][k8 + t4 + 4];
                af[mt][3] = As[row + 8][k8 + t4 + 4];
            }
            #pragma unroll
            for (int ntj = 0; ntj < 4; ntj++) {
                int col = wn + ntj * 8 + g;
                bf[ntj][0] = Bs[col][k8 + t4];
                bf[ntj][1] = Bs[col][k8 + t4 + 4];
            }
            #pragma unroll
            for (int mt = 0; mt < 4; mt++)
                #pragma unroll
                for (int ntj = 0; ntj < 4; ntj++) {
                    asm volatile(
                        "mma.sync.aligned.m16n8k8.row.col.f32.tf32.tf32.f32 "
                        "{%0,%1,%2,%3}, {%4,%5,%6,%7}, {%8,%9}, {%0,%1,%2,%3};"
                        : "+f"(c[mt][ntj][0]), "+f"(c[mt][ntj][1]),
                          "+f"(c[mt][ntj][2]), "+f"(c[mt][ntj][3])
                        : "r"(af[mt][0]), "r"(af[mt][1]), "r"(af[mt][2]), "r"(af[mt][3]),
                          "r"(bf[ntj][0]), "r"(bf[ntj][1]));
                }
        }
        if (more) {
            __syncthreads();
            #pragma unroll
            for (int i = 0; i < 4; i++) {
                int rr = r0 + 32 * i;
                As[rr][c4 + 0] = f2tf32(pa[i].x); As[rr][c4 + 1] = f2tf32(pa[i].y);
                As[rr][c4 + 2] = f2tf32(pa[i].z); As[rr][c4 + 3] = f2tf32(pa[i].w);
                Bs[rr][c4 + 0] = f2tf32(pb[i].x); Bs[rr][c4 + 1] = f2tf32(pb[i].y);
                Bs[rr][c4 + 2] = f2tf32(pb[i].z); Bs[rr][c4 + 3] = f2tf32(pb[i].w);
            }
            __syncthreads();
        }
    }

    #pragma unroll
    for (int mt = 0; mt < 4; mt++) {
        int row0 = bm + wm + mt * 16 + g;
        #pragma unroll
        for (int ntj = 0; ntj < 4; ntj++) {
            int col = bn + wn + ntj * 8 + t4 * 2;
            if (row0 < M && col + 1 < N) {
                C[(size_t)row0 * N + col]     = c[mt][ntj][0];
                C[(size_t)row0 * N + col + 1] = c[mt][ntj][1];
            }
            if (row0 + 8 < M && col + 1 < N) {
                C[(size_t)(row0 + 8) * N + col]     = c[mt][ntj][2];
                C[(size_t)(row0 + 8) * N + col + 1] = c[mt][ntj][3];
            }
        }
    }
}

// ---------------- per-(node,head) attention coefficients ---------------------
__global__ void k_alpha(const float* __restrict__ h,
                        const float* __restrict__ a_s, const float* __restrict__ a_d,
                        float* __restrict__ as_out, float* __restrict__ ad_out,
                        int n_nh, int Hh, int Cc)
{
    int warp = (blockIdx.x * blockDim.x + threadIdx.x) >> 5;
    int lane = threadIdx.x & 31;
    if (warp >= n_nh) return;
    int hh = warp % Hh;
    const float* hp  = h + (size_t)warp * Cc;
    const float* asp = a_s + hh * Cc;
    const float* adp = a_d + hh * Cc;
    float s = 0.f, d = 0.f;
    for (int c = lane; c < Cc; c += 32) {
        float v = hp[c];
        s += v * asp[c];
        d += v * adp[c];
    }
    #pragma unroll
    for (int o = 16; o > 0; o >>= 1) {
        s += __shfl_xor_sync(0xFFFFFFFFu, s, o);
        d += __shfl_xor_sync(0xFFFFFFFFu, d, o);
    }
    if (lane == 0) { as_out[warp] = s; ad_out[warp] = d; }
}

// ---------------- softmax layer 1: warp per dst node, 4 heads ----------------
__global__ __launch_bounds__(256) void k_softmax1()
{
    int w = (blockIdx.x * blockDim.x + threadIdx.x) >> 5;
    int lane = threadIdx.x & 31;
    if (w >= NN) return;
    int beg = g_rowptr[w], end = g_rowptr[w + 1];
    const float4* as4 = (const float4*)g_as1;
    float4 adv = ((const float4*)g_ad1)[w];
    float4 mx = make_float4(-1e30f, -1e30f, -1e30f, -1e30f);
    for (int i = beg + lane; i < end; i += 32) {
        float4 e = as4[g_srcidx[i]];
        e.x += adv.x; e.y += adv.y; e.z += adv.z; e.w += adv.w;
        e.x = (e.x > 0.f) ? e.x : NEG_SLOPE * e.x;
        e.y = (e.y > 0.f) ? e.y : NEG_SLOPE * e.y;
        e.z = (e.z > 0.f) ? e.z : NEG_SLOPE * e.z;
        e.w = (e.w > 0.f) ? e.w : NEG_SLOPE * e.w;
        g_alpha1[i] = e;
        mx.x = fmaxf(mx.x, e.x); mx.y = fmaxf(mx.y, e.y);
        mx.z = fmaxf(mx.z, e.z); mx.w = fmaxf(mx.w, e.w);
    }
    #pragma unroll
    for (int o = 16; o > 0; o >>= 1) {
        mx.x = fmaxf(mx.x, __shfl_xor_sync(0xFFFFFFFFu, mx.x, o));
        mx.y = fmaxf(mx.y, __shfl_xor_sync(0xFFFFFFFFu, mx.y, o));
        mx.z = fmaxf(mx.z, __shfl_xor_sync(0xFFFFFFFFu, mx.z, o));
        mx.w = fmaxf(mx.w, __shfl_xor_sync(0xFFFFFFFFu, mx.w, o));
    }
    float4 sum = make_float4(0.f, 0.f, 0.f, 0.f);
    for (int i = beg + lane; i < end; i += 32) {
        float4 e = g_alpha1[i];
        e.x = __expf(e.x - mx.x); e.y = __expf(e.y - mx.y);
        e.z = __expf(e.z - mx.z); e.w = __expf(e.w - mx.w);
        g_alpha1[i] = e;
        sum.x += e.x; sum.y += e.y; sum.z += e.z; sum.w += e.w;
    }
    #pragma unroll
    for (int o = 16; o > 0; o >>= 1) {
        sum.x += __shfl_xor_sync(0xFFFFFFFFu, sum.x, o);
        sum.y += __shfl_xor_sync(0xFFFFFFFFu, sum.y, o);
        sum.z += __shfl_xor_sync(0xFFFFFFFFu, sum.z, o);
        sum.w += __shfl_xor_sync(0xFFFFFFFFu, sum.w, o);
    }
    float4 rv = make_float4(1.f / sum.x, 1.f / sum.y, 1.f / sum.z, 1.f / sum.w);
    for (int i = beg + lane; i < end; i += 32) {
        float4 e = g_alpha1[i];
        e.x *= rv.x; e.y *= rv.y; e.z *= rv.z; e.w *= rv.w;
        g_alpha1[i] = e;
    }
}

// ---------------- softmax layer 2: warp per dst node, 1 head -----------------
__global__ __launch_bounds__(256) void k_softmax2()
{
    int w = (blockIdx.x * blockDim.x + threadIdx.x) >> 5;
    int lane = threadIdx.x & 31;
    if (w >= NN) return;
    int beg = g_rowptr[w], end = g_rowptr[w + 1];
    float adv = g_ad2[w];
    float mx = -1e30f;
    for (int i = beg + lane; i < end; i += 32) {
        float e = g_as2[g_srcidx[i]] + adv;
        e = (e > 0.f) ? e : NEG_SLOPE * e;
        g_alpha2[i] = e;
        mx = fmaxf(mx, e);
    }
    #pragma unroll
    for (int o = 16; o > 0; o >>= 1)
        mx = fmaxf(mx, __shfl_xor_sync(0xFFFFFFFFu, mx, o));
    float sum = 0.f;
    for (int i = beg + lane; i < end; i += 32) {
        float e = __expf(g_alpha2[i] - mx);
        g_alpha2[i] = e;
        sum += e;
    }
    #pragma unroll
    for (int o = 16; o > 0; o >>= 1)
        sum += __shfl_xor_sync(0xFFFFFFFFu, sum, o);
    float rv = 1.f / sum;
    for (int i = beg + lane; i < end; i += 32)
        g_alpha2[i] *= rv;
}

// ---- aggregation layer 1: 64 threads per dst row, fused +b1 and elu ---------
__global__ __launch_bounds__(256) void k_agg1(const float* __restrict__ b1)
{
    int row = blockIdx.x * 4 + (threadIdx.x >> 6);
    if (row >= NN) return;
    int q = threadIdx.x & 63;
    int head = q >> 4;
    int beg = g_rowptr[row], end = g_rowptr[row + 1];
    float4 acc = make_float4(0.f, 0.f, 0.f, 0.f);
    for (int i = beg; i < end; i++) {
        int s = g_srcidx[i];
        float4 a4 = g_alpha1[i];
        float a = (head == 0) ? a4.x : (head == 1) ? a4.y : (head == 2) ? a4.z : a4.w;
        float4 hv = *(const float4*)(g_h1 + (size_t)s * HC1 + q * 4);
        acc.x += a * hv.x; acc.y += a * hv.y; acc.z += a * hv.z; acc.w += a * hv.w;
    }
    float4 bb = *(const float4*)(b1 + q * 4);
    acc.x += bb.x; acc.y += bb.y; acc.z += bb.z; acc.w += bb.w;
    acc.x = (acc.x > 0.f) ? acc.x : expm1f(acc.x);
    acc.y = (acc.y > 0.f) ? acc.y : expm1f(acc.y);
    acc.z = (acc.z > 0.f) ? acc.z : expm1f(acc.z);
    acc.w = (acc.w > 0.f) ? acc.w : expm1f(acc.w);
    *(float4*)(g_x2 + (size_t)row * HC1 + q * 4) = acc;
}

// ---- aggregation layer 2: 16 threads per dst row, fused +b2, writes d_out ---
__global__ __launch_bounds__(256) void k_agg2(const float* __restrict__ b2,
                                              float* __restrict__ out)
{
    int row = blockIdx.x * 16 + (threadIdx.x >> 4);
    if (row >= NN) return;
    int q = threadIdx.x & 15;
    int beg = g_rowptr[row], end = g_rowptr[row + 1];
    float4 acc = make_float4(0.f, 0.f, 0.f, 0.f);
    for (int i = beg; i < end; i++) {
        int s = g_srcidx[i];
        float a = g_alpha2[i];
        float4 hv = *(const float4*)(g_h2 + (size_t)s * OC + q * 4);
        acc.x += a * hv.x; acc.y += a * hv.y; acc.z += a * hv.z; acc.w += a * hv.w;
    }
    float4 bb = *(const float4*)(b2 + q * 4);
    acc.x += bb.x; acc.y += bb.y; acc.z += bb.z; acc.w += bb.w;
    *(float4*)(out + (size_t)row * OC + q * 4) = acc;
}

// =============================================================================
extern "C" void kernel_launch(void* const* d_in, const int* in_sizes, int n_in,
                              void* d_out, int out_size)
{
    const float* x     = (const float*)d_in[0];
    const int*   ei    = (const int*)d_in[1];
    const float* W1    = (const float*)d_in[2];
    const float* a_s1  = (const float*)d_in[3];
    const float* a_d1  = (const float*)d_in[4];
    const float* b1    = (const float*)d_in[5];
    const float* W2    = (const float*)d_in[6];
    const float* a_s2  = (const float*)d_in[7];
    const float* a_d2  = (const float*)d_in[8];
    const float* b2    = (const float*)d_in[9];
    float*       out   = (float*)d_out;

    float *h1, *x2, *as1, *ad1, *h2, *as2, *ad2;
    cudaGetSymbolAddress((void**)&h1,  g_h1);
    cudaGetSymbolAddress((void**)&x2,  g_x2);
    cudaGetSymbolAddress((void**)&as1, g_as1);
    cudaGetSymbolAddress((void**)&ad1, g_ad1);
    cudaGetSymbolAddress((void**)&h2,  g_h2);
    cudaGetSymbolAddress((void**)&as2, g_as2);
    cudaGetSymbolAddress((void**)&ad2, g_ad2);

    // ---- CSR build (shared by both layers) ----
    k_zero_deg<<<(NN + 255) / 256, 256>>>();
    k_count<<<(EP + 255) / 256, 256>>>(ei);
    k_scan1<<<NTILES, SCAN_T>>>();
    k_scan2<<<1, 32>>>();
    k_scan3<<<NTILES, SCAN_T>>>();
    k_setcur<<<(NN + 255) / 256, 256>>>();
    k_scatter<<<(EP + 255) / 256, 256>>>(ei);

    // ---- layer 1 ----
    {
        dim3 grid((HC1 + TBN - 1) / TBN, (NN + TBM - 1) / TBM);
        k_tf32gemm<<<grid, 256>>>(x, W1, h1, NN, HC1, INC);
    }
    {
        int warps = NN * H1;
        k_alpha<<<(warps * 32 + 255) / 256, 256>>>(h1, a_s1, a_d1, as1, ad1, warps, H1, C1);
    }
    k_softmax1<<<(NN * 32 + 255) / 256, 256>>>();
    k_agg1<<<(NN + 3) / 4, 256>>>(b1);

    // ---- layer 2 ----
    {
        dim3 grid((OC + TBN - 1) / TBN, (NN + TBM - 1) / TBM);
        k_tf32gemm<<<grid, 256>>>(x2, W2, h2, NN, OC, HC1);
    }
    {
        int warps = NN;
        k_alpha<<<(warps * 32 + 255) / 256, 256>>>(h2, a_s2, a_d2, as2, ad2, warps, 1, OC);
    }
    k_softmax2<<<(NN * 32 + 255) / 256, 256>>>();
    k_agg2<<<(NN + 15) / 16, 256>>>(b2, out);
}

// round 6
// speedup vs baseline: 4.9064x; 1.0613x over previous
#include <cuda_runtime.h>
#include <cuda_bf16.h>
#include <math.h>

// ---------------- problem constants ----------------
#define NN    50000
#define EE    800000
#define EP    850000          // EE + NN self loops
#define INC   1024
#define H1    4
#define C1    64
#define HC1   256             // H1*C1
#define OC    64
#define NEG_SLOPE 0.2f

#define SCAN_T 512
#define NTILES ((NN + SCAN_T - 1) / SCAN_T)

// ---------------- scratch (device globals) ----------------
__device__ float  g_h1[(size_t)NN * HC1];
__device__ float  g_x2[(size_t)NN * HC1];
__device__ float  g_as1[NN * H1];
__device__ float  g_ad1[NN * H1];
__device__ float4 g_alpha1[EP];               // per-edge exp values (4 heads), CSR order
__device__ float4 g_rd1[NN];                  // reciprocal softmax denominators

__device__ float  g_h2[(size_t)NN * OC];
__device__ float  g_as2[NN];
__device__ float  g_ad2[NN];
__device__ float  g_alpha2[EP];
__device__ float  g_rd2[NN];

// CSR
__device__ int g_deg[NN];
__device__ int g_rowptr[NN + 1];
__device__ int g_cursor[NN];
__device__ int g_srcidx[EP];
__device__ int g_bsum[NTILES];

__device__ __forceinline__ unsigned f2tf32(float f) {
    unsigned r;
    asm("cvt.rna.tf32.f32 %0, %1;" : "=r"(r) : "f"(f));
    return r;
}

// ================= init + CSR construction =================
__global__ void k_zero() {
    int i = blockIdx.x * blockDim.x + threadIdx.x;
    if (i >= NN) return;
    g_deg[i] = 0;
    g_as2[i] = 0.f; g_ad2[i] = 0.f;
    float4 z = make_float4(0.f, 0.f, 0.f, 0.f);
    ((float4*)g_as1)[i] = z;
    ((float4*)g_ad1)[i] = z;
}
__global__ void k_count(const int* __restrict__ ei) {
    int e = blockIdx.x * blockDim.x + threadIdx.x;
    if (e >= EP) return;
    int dn = (e < EE) ? ei[EE + e] : (e - EE);
    atomicAdd(&g_deg[dn], 1);
}
__global__ __launch_bounds__(SCAN_T) void k_scan1() {
    __shared__ int s[SCAN_T];
    int tid = threadIdx.x;
    int i = blockIdx.x * SCAN_T + tid;
    int v = (i < NN) ? g_deg[i] : 0;
    s[tid] = v;
    __syncthreads();
    #pragma unroll
    for (int off = 1; off < SCAN_T; off <<= 1) {
        int t = (tid >= off) ? s[tid - off] : 0;
        __syncthreads();
        s[tid] += t;
        __syncthreads();
    }
    if (i < NN) g_rowptr[i + 1] = s[tid];
    if (tid == SCAN_T - 1) g_bsum[blockIdx.x] = s[tid];
}
__global__ void k_scan2() {
    if (threadIdx.x == 0) {
        int run = 0;
        for (int t = 0; t < NTILES; t++) { int v = g_bsum[t]; g_bsum[t] = run; run += v; }
        g_rowptr[0] = 0;
    }
}
__global__ __launch_bounds__(SCAN_T) void k_scan3() {
    int i = blockIdx.x * SCAN_T + threadIdx.x;
    if (i < NN) g_rowptr[i + 1] += g_bsum[blockIdx.x];
}
__global__ void k_setcur() {
    int i = blockIdx.x * blockDim.x + threadIdx.x;
    if (i < NN) g_cursor[i] = g_rowptr[i];
}
__global__ void k_scatter(const int* __restrict__ ei) {
    int e = blockIdx.x * blockDim.x + threadIdx.x;
    if (e >= EP) return;
    int s, dn;
    if (e < EE) { s = ei[e]; dn = ei[EE + e]; }
    else        { s = e - EE; dn = s; }
    int pos = atomicAdd(&g_cursor[dn], 1);
    g_srcidx[pos] = s;
}

// ============= TF32 GEMM + fused attention-coefficient epilogue ==============
// C[m,n] = sum_k A[m,k]*B[n,k];  as_out[m*heads+n/64] += C[m,n]*avs[n] (likewise ad)
#define TBM 128
#define TBN 128
#define TBK 32
#define TSS 36
#define GEMM_SMEM_BYTES (4 * TBM * TSS * 4)   // 2 bufs x (A,B) x 128x36 u32

__global__ __launch_bounds__(256) void k_tf32gemm(
    const float* __restrict__ A, const float* __restrict__ B,
    float* __restrict__ C, int M, int N, int K,
    const float* __restrict__ avs, const float* __restrict__ avd,
    float* __restrict__ as_out, float* __restrict__ ad_out, int heads)
{
    extern __shared__ unsigned smem_u[];
    unsigned* Abase = smem_u;                    // [2][TBM][TSS]
    unsigned* Bbase = smem_u + 2 * TBM * TSS;    // [2][TBN][TSS]

    int tid = threadIdx.x;
    int bm = blockIdx.y * TBM, bn = blockIdx.x * TBN;
    int wid = tid >> 5, lane = tid & 31;
    int wm = (wid >> 2) * 64;
    int wn = (wid & 3) * 32;
    int g  = lane >> 2;
    int t4 = lane & 3;

    int r0 = tid >> 3;
    int c4 = (tid & 7) * 4;

    float c[4][4][4];
    #pragma unroll
    for (int i = 0; i < 4; i++)
        #pragma unroll
        for (int j = 0; j < 4; j++)
            #pragma unroll
            for (int r = 0; r < 4; r++) c[i][j][r] = 0.f;

    const float4 zero4 = make_float4(0.f, 0.f, 0.f, 0.f);
    float4 pa[4], pb[4];
    int nt = K / TBK;

    // fetch tile 0
    #pragma unroll
    for (int i = 0; i < 4; i++) {
        int ar = bm + r0 + 32 * i;
        pa[i] = (ar < M) ? *(const float4*)(A + (size_t)ar * K + c4) : zero4;
        int br = bn + r0 + 32 * i;
        pb[i] = (br < N) ? *(const float4*)(B + (size_t)br * K + c4) : zero4;
    }
    // store tile 0 -> buf 0
    {
        unsigned* Ab = Abase;
        unsigned* Bb = Bbase;
        #pragma unroll
        for (int i = 0; i < 4; i++) {
            int rr = r0 + 32 * i;
            Ab[rr * TSS + c4 + 0] = f2tf32(pa[i].x); Ab[rr * TSS + c4 + 1] = f2tf32(pa[i].y);
            Ab[rr * TSS + c4 + 2] = f2tf32(pa[i].z); Ab[rr * TSS + c4 + 3] = f2tf32(pa[i].w);
            Bb[rr * TSS + c4 + 0] = f2tf32(pb[i].x); Bb[rr * TSS + c4 + 1] = f2tf32(pb[i].y);
            Bb[rr * TSS + c4 + 2] = f2tf32(pb[i].z); Bb[rr * TSS + c4 + 3] = f2tf32(pb[i].w);
        }
    }
    __syncthreads();

    for (int t = 0; t < nt; t++) {
        int cur = t & 1;
        bool more = (t + 1 < nt);
        if (more) {
            int k0 = (t + 1) * TBK;
            #pragma unroll
            for (int i = 0; i < 4; i++) {
                int ar = bm + r0 + 32 * i;
                pa[i] = (ar < M) ? *(const float4*)(A + (size_t)ar * K + k0 + c4) : zero4;
                int br = bn + r0 + 32 * i;
                pb[i] = (br < N) ? *(const float4*)(B + (size_t)br * K + k0 + c4) : zero4;
            }
        }
        const unsigned* Ab = Abase + cur * TBM * TSS;
        const unsigned* Bb = Bbase + cur * TBM * TSS;
        #pragma unroll
        for (int ks = 0; ks < 4; ks++) {
            int k8 = ks * 8;
            unsigned af[4][4], bf[4][2];
            #pragma unroll
            for (int mt = 0; mt < 4; mt++) {
                int row = wm + mt * 16 + g;
                af[mt][0] = Ab[row * TSS + k8 + t4];
                af[mt][1] = Ab[(row + 8) * TSS + k8 + t4];
                af[mt][2] = Ab[row * TSS + k8 + t4 + 4];
                af[mt][3] = Ab[(row + 8) * TSS + k8 + t4 + 4];
            }
            #pragma unroll
            for (int ntj = 0; ntj < 4; ntj++) {
                int col = wn + ntj * 8 + g;
                bf[ntj][0] = Bb[col * TSS + k8 + t4];
                bf[ntj][1] = Bb[col * TSS + k8 + t4 + 4];
            }
            #pragma unroll
            for (int mt = 0; mt < 4; mt++)
                #pragma unroll
                for (int ntj = 0; ntj < 4; ntj++) {
                    asm volatile(
                        "mma.sync.aligned.m16n8k8.row.col.f32.tf32.tf32.f32 "
                        "{%0,%1,%2,%3}, {%4,%5,%6,%7}, {%8,%9}, {%0,%1,%2,%3};"
                        : "+f"(c[mt][ntj][0]), "+f"(c[mt][ntj][1]),
                          "+f"(c[mt][ntj][2]), "+f"(c[mt][ntj][3])
                        : "r"(af[mt][0]), "r"(af[mt][1]), "r"(af[mt][2]), "r"(af[mt][3]),
                          "r"(bf[ntj][0]), "r"(bf[ntj][1]));
                }
        }
        if (more) {
            int nx = cur ^ 1;
            unsigned* Aw = Abase + nx * TBM * TSS;
            unsigned* Bw = Bbase + nx * TBM * TSS;
            #pragma unroll
            for (int i = 0; i < 4; i++) {
                int rr = r0 + 32 * i;
                Aw[rr * TSS + c4 + 0] = f2tf32(pa[i].x); Aw[rr * TSS + c4 + 1] = f2tf32(pa[i].y);
                Aw[rr * TSS + c4 + 2] = f2tf32(pa[i].z); Aw[rr * TSS + c4 + 3] = f2tf32(pa[i].w);
                Bw[rr * TSS + c4 + 0] = f2tf32(pb[i].x); Bw[rr * TSS + c4 + 1] = f2tf32(pb[i].y);
                Bw[rr * TSS + c4 + 2] = f2tf32(pb[i].z); Bw[rr * TSS + c4 + 3] = f2tf32(pb[i].w);
            }
            __syncthreads();
        }
    }

    // ---- C store ----
    #pragma unroll
    for (int mt = 0; mt < 4; mt++) {
        int row0 = bm + wm + mt * 16 + g;
        #pragma unroll
        for (int ntj = 0; ntj < 4; ntj++) {
            int col = bn + wn + ntj * 8 + t4 * 2;
            if (row0 < M && col + 1 < N) {
                C[(size_t)row0 * N + col]     = c[mt][ntj][0];
                C[(size_t)row0 * N + col + 1] = c[mt][ntj][1];
            }
            if (row0 + 8 < M && col + 1 < N) {
                C[(size_t)(row0 + 8) * N + col]     = c[mt][ntj][2];
                C[(size_t)(row0 + 8) * N + col + 1] = c[mt][ntj][3];
            }
        }
    }

    // ---- fused attention-coefficient partials ----
    int head = (bn + wn) >> 6;     // all cols of this thread lie in one 64-wide head
    if (head < heads) {
        float asac[4][2] = {}, adac[4][2] = {};
        #pragma unroll
        for (int mt = 0; mt < 4; mt++)
            #pragma unroll
            for (int ntj = 0; ntj < 4; ntj++) {
                int colb = bn + wn + ntj * 8 + t4 * 2;
                if (colb + 1 < N) {
                    float s0 = avs[colb], s1 = avs[colb + 1];
                    float d0 = avd[colb], d1 = avd[colb + 1];
                    asac[mt][0] += c[mt][ntj][0] * s0 + c[mt][ntj][1] * s1;
                    adac[mt][0] += c[mt][ntj][0] * d0 + c[mt][ntj][1] * d1;
                    asac[mt][1] += c[mt][ntj][2] * s0 + c[mt][ntj][3] * s1;
                    adac[mt][1] += c[mt][ntj][2] * d0 + c[mt][ntj][3] * d1;
                }
            }
        #pragma unroll
        for (int mt = 0; mt < 4; mt++)
            #pragma unroll
            for (int hf = 0; hf < 2; hf++) {
                float v = asac[mt][hf];
                float w = adac[mt][hf];
                v += __shfl_xor_sync(0xFFFFFFFFu, v, 1);
                v += __shfl_xor_sync(0xFFFFFFFFu, v, 2);
                w += __shfl_xor_sync(0xFFFFFFFFu, w, 1);
                w += __shfl_xor_sync(0xFFFFFFFFu, w, 2);
                int row = bm + wm + mt * 16 + g + hf * 8;
                if (t4 == 0 && row < M) {
                    atomicAdd(&as_out[row * heads + head], v);
                    atomicAdd(&ad_out[row * heads + head], w);
                }
            }
    }
}

// ---------------- softmax layer 1: warp per dst node, 4 heads ----------------
__global__ __launch_bounds__(256) void k_softmax1()
{
    int w = (blockIdx.x * blockDim.x + threadIdx.x) >> 5;
    int lane = threadIdx.x & 31;
    if (w >= NN) return;
    int beg = g_rowptr[w], end = g_rowptr[w + 1];
    const float4* as4 = (const float4*)g_as1;
    float4 adv = ((const float4*)g_ad1)[w];
    float4 mx = make_float4(-1e30f, -1e30f, -1e30f, -1e30f);
    for (int i = beg + lane; i < end; i += 32) {
        float4 e = as4[g_srcidx[i]];
        e.x += adv.x; e.y += adv.y; e.z += adv.z; e.w += adv.w;
        e.x = (e.x > 0.f) ? e.x : NEG_SLOPE * e.x;
        e.y = (e.y > 0.f) ? e.y : NEG_SLOPE * e.y;
        e.z = (e.z > 0.f) ? e.z : NEG_SLOPE * e.z;
        e.w = (e.w > 0.f) ? e.w : NEG_SLOPE * e.w;
        g_alpha1[i] = e;
        mx.x = fmaxf(mx.x, e.x); mx.y = fmaxf(mx.y, e.y);
        mx.z = fmaxf(mx.z, e.z); mx.w = fmaxf(mx.w, e.w);
    }
    #pragma unroll
    for (int o = 16; o > 0; o >>= 1) {
        mx.x = fmaxf(mx.x, __shfl_xor_sync(0xFFFFFFFFu, mx.x, o));
        mx.y = fmaxf(mx.y, __shfl_xor_sync(0xFFFFFFFFu, mx.y, o));
        mx.z = fmaxf(mx.z, __shfl_xor_sync(0xFFFFFFFFu, mx.z, o));
        mx.w = fmaxf(mx.w, __shfl_xor_sync(0xFFFFFFFFu, mx.w, o));
    }
    float4 sum = make_float4(0.f, 0.f, 0.f, 0.f);
    for (int i = beg + lane; i < end; i += 32) {
        float4 e = g_alpha1[i];
        e.x = __expf(e.x - mx.x); e.y = __expf(e.y - mx.y);
        e.z = __expf(e.z - mx.z); e.w = __expf(e.w - mx.w);
        g_alpha1[i] = e;
        sum.x += e.x; sum.y += e.y; sum.z += e.z; sum.w += e.w;
    }
    #pragma unroll
    for (int o = 16; o > 0; o >>= 1) {
        sum.x += __shfl_xor_sync(0xFFFFFFFFu, sum.x, o);
        sum.y += __shfl_xor_sync(0xFFFFFFFFu, sum.y, o);
        sum.z += __shfl_xor_sync(0xFFFFFFFFu, sum.z, o);
        sum.w += __shfl_xor_sync(0xFFFFFFFFu, sum.w, o);
    }
    if (lane == 0)
        g_rd1[w] = make_float4(1.f / sum.x, 1.f / sum.y, 1.f / sum.z, 1.f / sum.w);
}

// ---------------- softmax layer 2 --------------------------------------------
__global__ __launch_bounds__(256) void k_softmax2()
{
    int w = (blockIdx.x * blockDim.x + threadIdx.x) >> 5;
    int lane = threadIdx.x & 31;
    if (w >= NN) return;
    int beg = g_rowptr[w], end = g_rowptr[w + 1];
    float adv = g_ad2[w];
    float mx = -1e30f;
    for (int i = beg + lane; i < end; i += 32) {
        float e = g_as2[g_srcidx[i]] + adv;
        e = (e > 0.f) ? e : NEG_SLOPE * e;
        g_alpha2[i] = e;
        mx = fmaxf(mx, e);
    }
    #pragma unroll
    for (int o = 16; o > 0; o >>= 1)
        mx = fmaxf(mx, __shfl_xor_sync(0xFFFFFFFFu, mx, o));
    float sum = 0.f;
    for (int i = beg + lane; i < end; i += 32) {
        float e = __expf(g_alpha2[i] - mx);
        g_alpha2[i] = e;
        sum += e;
    }
    #pragma unroll
    for (int o = 16; o > 0; o >>= 1)
        sum += __shfl_xor_sync(0xFFFFFFFFu, sum, o);
    if (lane == 0) g_rd2[w] = 1.f / sum;
}

// ---- aggregation layer 1: 64 threads per dst row, fused +b1 and elu ---------
__global__ __launch_bounds__(256) void k_agg1(const float* __restrict__ b1)
{
    int row = blockIdx.x * 4 + (threadIdx.x >> 6);
    if (row >= NN) return;
    int q = threadIdx.x & 63;
    int head = q >> 4;
    int beg = g_rowptr[row], end = g_rowptr[row + 1];
    float4 rdv = g_rd1[row];
    float rd = (head == 0) ? rdv.x : (head == 1) ? rdv.y : (head == 2) ? rdv.z : rdv.w;
    float4 acc = make_float4(0.f, 0.f, 0.f, 0.f);
    for (int i = beg; i < end; i++) {
        int s = g_srcidx[i];
        float4 a4 = g_alpha1[i];
        float a = ((head == 0) ? a4.x : (head == 1) ? a4.y : (head == 2) ? a4.z : a4.w) * rd;
        float4 hv = *(const float4*)(g_h1 + (size_t)s * HC1 + q * 4);
        acc.x += a * hv.x; acc.y += a * hv.y; acc.z += a * hv.z; acc.w += a * hv.w;
    }
    float4 bb = *(const float4*)(b1 + q * 4);
    acc.x += bb.x; acc.y += bb.y; acc.z += bb.z; acc.w += bb.w;
    acc.x = (acc.x > 0.f) ? acc.x : expm1f(acc.x);
    acc.y = (acc.y > 0.f) ? acc.y : expm1f(acc.y);
    acc.z = (acc.z > 0.f) ? acc.z : expm1f(acc.z);
    acc.w = (acc.w > 0.f) ? acc.w : expm1f(acc.w);
    *(float4*)(g_x2 + (size_t)row * HC1 + q * 4) = acc;
}

// ---- aggregation layer 2: 16 threads per dst row, fused +b2, writes d_out ---
__global__ __launch_bounds__(256) void k_agg2(const float* __restrict__ b2,
                                              float* __restrict__ out)
{
    int row = blockIdx.x * 16 + (threadIdx.x >> 4);
    if (row >= NN) return;
    int q = threadIdx.x & 15;
    int beg = g_rowptr[row], end = g_rowptr[row + 1];
    float rd = g_rd2[row];
    float4 acc = make_float4(0.f, 0.f, 0.f, 0.f);
    for (int i = beg; i < end; i++) {
        int s = g_srcidx[i];
        float a = g_alpha2[i] * rd;
        float4 hv = *(const float4*)(g_h2 + (size_t)s * OC + q * 4);
        acc.x += a * hv.x; acc.y += a * hv.y; acc.z += a * hv.z; acc.w += a * hv.w;
    }
    float4 bb = *(const float4*)(b2 + q * 4);
    acc.x += bb.x; acc.y += bb.y; acc.z += bb.z; acc.w += bb.w;
    *(float4*)(out + (size_t)row * OC + q * 4) = acc;
}

// =============================================================================
extern "C" void kernel_launch(void* const* d_in, const int* in_sizes, int n_in,
                              void* d_out, int out_size)
{
    const float* x     = (const float*)d_in[0];
    const int*   ei    = (const int*)d_in[1];
    const float* W1    = (const float*)d_in[2];
    const float* a_s1  = (const float*)d_in[3];
    const float* a_d1  = (const float*)d_in[4];
    const float* b1    = (const float*)d_in[5];
    const float* W2    = (const float*)d_in[6];
    const float* a_s2  = (const float*)d_in[7];
    const float* a_d2  = (const float*)d_in[8];
    const float* b2    = (const float*)d_in[9];
    float*       out   = (float*)d_out;

    float *h1, *x2, *as1, *ad1, *h2, *as2, *ad2;
    cudaGetSymbolAddress((void**)&h1,  g_h1);
    cudaGetSymbolAddress((void**)&x2,  g_x2);
    cudaGetSymbolAddress((void**)&as1, g_as1);
    cudaGetSymbolAddress((void**)&ad1, g_ad1);
    cudaGetSymbolAddress((void**)&h2,  g_h2);
    cudaGetSymbolAddress((void**)&as2, g_as2);
    cudaGetSymbolAddress((void**)&ad2, g_ad2);

    cudaFuncSetAttribute(k_tf32gemm,
                         cudaFuncAttributeMaxDynamicSharedMemorySize, GEMM_SMEM_BYTES);

    // ---- init + CSR build ----
    k_zero<<<(NN + 255) / 256, 256>>>();
    k_count<<<(EP + 255) / 256, 256>>>(ei);
    k_scan1<<<NTILES, SCAN_T>>>();
    k_scan2<<<1, 32>>>();
    k_scan3<<<NTILES, SCAN_T>>>();
    k_setcur<<<(NN + 255) / 256, 256>>>();
    k_scatter<<<(EP + 255) / 256, 256>>>(ei);

    // ---- layer 1 ----
    {
        dim3 grid((HC1 + TBN - 1) / TBN, (NN + TBM - 1) / TBM);
        k_tf32gemm<<<grid, 256, GEMM_SMEM_BYTES>>>(x, W1, h1, NN, HC1, INC,
                                                   a_s1, a_d1, as1, ad1, H1);
    }
    k_softmax1<<<(NN * 32 + 255) / 256, 256>>>();
    k_agg1<<<(NN + 3) / 4, 256>>>(b1);

    // ---- layer 2 ----
    {
        dim3 grid((OC + TBN - 1) / TBN, (NN + TBM - 1) / TBM);
        k_tf32gemm<<<grid, 256, GEMM_SMEM_BYTES>>>(x2, W2, h2, NN, OC, HC1,
                                                   a_s2, a_d2, as2, ad2, 1);
    }
    k_softmax2<<<(NN * 32 + 255) / 256, 256>>>();
    k_agg2<<<(NN + 15) / 16, 256>>>(b2, out);
}